// round 7
// baseline (speedup 1.0000x reference)
#include <cuda_runtime.h>

#define NFSZ 1001
#define HSZ   256
#define BSZ   64
#define FD    128
#define INCH  16
#define G4    1024   // 4*H
#define INS0  144    // FD + INCH

// scratch (device globals: allocation-free rule)
__device__ float g_Gf[NFSZ * G4];                    // pre-scaled f-side gate pre-acts
__device__ unsigned long long g_mb[2 * BSZ * 1024];  // inter-layer mailboxes {val,tag}

__device__ __forceinline__ float ex2f(float x) {
    float y; asm("ex2.approx.f32 %0, %1;" : "=f"(y) : "f"(x)); return y;
}
__device__ __forceinline__ float rcpf(float x) {
    float y; asm("rcp.approx.f32 %0, %1;" : "=f"(y) : "f"(x)); return y;
}
__device__ __forceinline__ float negabsf(float x) {
    return __int_as_float(__float_as_int(x) | 0x80000000);
}
__device__ __forceinline__ unsigned long long ldv64(const unsigned long long* p) {
    unsigned long long v;
    asm volatile("ld.volatile.global.b64 %0, [%1];" : "=l"(v) : "l"(p));
    return v;
}
__device__ __forceinline__ void stv64(unsigned long long* p, unsigned long long v) {
    asm volatile("st.volatile.global.b64 [%0], %1;" :: "l"(p), "l"(v) : "memory");
}

#define L2E   1.4426950408889634f
#define NL2E2 -2.8853900817779268f

// ---------------- fused precompute: Gf = scale * (f @ Wf^T) ----------------
// Block: 256 threads -> 256 g (one per thread), 8 timesteps. k in chunks of 32,
// W chunk staged in smem (coalesced loads), so no separate transpose kernel.

__global__ __launch_bounds__(256) void gf_kernel(const float* __restrict__ f,
                                                 const float* __restrict__ Wih0) {
    __shared__ float Wc[256][33];   // [local g][k-chunk], padded
    __shared__ float fs[8][32];
    const int tid = threadIdx.x;
    const int t0  = blockIdx.x * 8;
    const int gb  = blockIdx.y * 256;     // gate = blockIdx.y (256 g per gate)

    float acc[8] = {0.f,0.f,0.f,0.f,0.f,0.f,0.f,0.f};

    for (int kc = 0; kc < FD; kc += 32) {
        // stage W chunk: 256 g x 32 k (each warp loads one 128B row segment)
        #pragma unroll
        for (int i = 0; i < 32; i++) {
            int e  = i * 256 + tid;
            int gl = e >> 5, kk = e & 31;
            Wc[gl][kk] = Wih0[(gb + gl) * INS0 + kc + kk];
        }
        // stage f chunk: 8 t x 32 k
        {
            int tt = tid >> 5, kk = tid & 31;
            float v = 0.f;
            int t = t0 + tt;
            if (t < NFSZ) v = f[t * FD + kc + kk];
            fs[tt][kk] = v;
        }
        __syncthreads();
        #pragma unroll 8
        for (int kk = 0; kk < 32; kk++) {
            float w = Wc[tid][kk];
            #pragma unroll
            for (int tt = 0; tt < 8; tt++) acc[tt] = fmaf(fs[tt][kk], w, acc[tt]);
        }
        __syncthreads();
    }
    float scale = (blockIdx.y == 2) ? NL2E2 : -L2E;
    #pragma unroll
    for (int tt = 0; tt < 8; tt++) {
        int t = t0 + tt;
        if (t < NFSZ) g_Gf[t * G4 + gb + tid] = acc[tt] * scale;
    }
}

// ---------------- main LSTM: one CTA per (batch, layer) ----------------
// 192 CTAs x 128 threads, 2 hidden units per thread. Intra-layer recurrence:
// 3-level shfl -> 4 smem partials (parity-buffered) -> one 4-warp bar per tick.
// Inter-layer: tagged 1001-slot gmem mailboxes; consumers self-time by spin.

__global__ __launch_bounds__(128, 2) void lstm_kernel(
    const float* __restrict__ x,
    const float* __restrict__ Wih0, const float* __restrict__ Whh0,
    const float* __restrict__ bih0, const float* __restrict__ bhh0,
    const float* __restrict__ Whr0,
    const float* __restrict__ Wih1, const float* __restrict__ Whh1,
    const float* __restrict__ bih1, const float* __restrict__ bhh1,
    const float* __restrict__ Whr1,
    const float* __restrict__ Wih2, const float* __restrict__ Whh2,
    const float* __restrict__ bih2, const float* __restrict__ bhh2,
    const float* __restrict__ Whr2,
    float* __restrict__ out)
{
    __shared__ __align__(16) float part[2][4];   // [parity][warp partial]

    const int blk   = blockIdx.x;
    const int b     = blk / 3;
    const int layer = blk - b * 3;
    const int tid   = threadIdx.x;
    const int warp  = tid >> 5;
    const int lane  = tid & 31;
    const int u0    = tid * 2;

    const float* Whh = (layer == 0) ? Whh0 : (layer == 1) ? Whh1 : Whh2;
    const float* Wih = (layer == 1) ? Wih1 : Wih2;
    const float* bih = (layer == 0) ? bih0 : (layer == 1) ? bih1 : bih2;
    const float* bhh = (layer == 0) ? bhh0 : (layer == 1) ? bhh1 : bhh2;
    const float* Whr = (layer == 0) ? Whr0 : (layer == 1) ? Whr1 : Whr2;

    // j = gate*2 + m
    float whh_s[8], base_s[8], wih_s[8];
    #pragma unroll
    for (int j = 0; j < 8; j++) {
        int gate = j >> 1;
        int idx  = gate * HSZ + u0 + (j & 1);
        float sc = (gate == 2) ? NL2E2 : -L2E;
        whh_s[j] = Whh[idx] * sc;
        float bias = bih[idx] + bhh[idx];
        if (layer == 0) {
            float acc = bias;   // fold batch-constant x contribution
            #pragma unroll
            for (int kk = 0; kk < INCH; kk++)
                acc = fmaf(x[b * INCH + kk], Wih0[idx * INS0 + FD + kk], acc);
            base_s[j] = acc * sc;
            wih_s[j]  = 0.f;
        } else {
            base_s[j] = bias * sc;
            wih_s[j]  = Wih[idx] * sc;
        }
    }
    const float w0 = Whr[u0], w1 = Whr[u0 + 1];
    float cs0 = 0.f, cs1 = 0.f;   // plain cell states (R5 formulation)

    if (tid < 4) { part[0][tid] = 0.f; part[1][tid] = 0.f; }
    __syncthreads();

    unsigned long long* mbin  = &g_mb[((layer - 1) * BSZ + b) * 1024];  // layer>0
    unsigned long long* mbout = &g_mb[(layer * BSZ + b) * 1024];        // layer<2

    // layer0: Gf double buffer (pre-added with base)
    float gfc[8], gfn[8];
    if (layer == 0) {
        #pragma unroll
        for (int g4 = 0; g4 < 4; g4++) {
            float2 v = *(const float2*)&g_Gf[g4 * HSZ + u0];
            gfc[2 * g4]     = v.x + base_s[2 * g4];
            gfc[2 * g4 + 1] = v.y + base_s[2 * g4 + 1];
        }
    }
    unsigned long long mv = 0;
    if (layer > 0) mv = ldv64(&mbin[0]);

    for (int tk = 0; tk <= NFSZ; tk++) {
        const int par = tk & 1, rp = par ^ 1;

        // off-chain prefetch of next tick's Gf row (layer 0)
        if (layer == 0 && (tk + 1) < NFSZ) {
            const float* gp = &g_Gf[(tk + 1) * G4 + u0];
            #pragma unroll
            for (int g4 = 0; g4 < 4; g4++) {
                float2 v = *(const float2*)(gp + g4 * HSZ);
                gfn[2 * g4]     = v.x + base_s[2 * g4];
                gfn[2 * g4 + 1] = v.y + base_s[2 * g4 + 1];
            }
        }

        // materialize h(tk-1): sum this layer's 4 warp partials
        float4 p = *(const float4*)part[rp];
        float h_prev = (p.x + p.y) + (p.z + p.w);

        if (tk >= 1 && tid == 0) {
            if (layer < 2) {
                unsigned long long pk =
                    (unsigned long long)(unsigned)__float_as_int(h_prev)
                    | ((unsigned long long)(unsigned)tk << 32);   // slot tk-1, tag tk
                stv64(&mbout[tk - 1], pk);
            } else {
                out[b * NFSZ + (tk - 1)] = h_prev;
            }
        }

        if (tk < NFSZ) {
            // resolve this timestep's inter-layer input
            float u_in = 0.f;
            if (layer > 0) {
                const unsigned expf = (unsigned)(tk + 1);
                while ((unsigned)(mv >> 32) != expf) mv = ldv64(&mbin[tk]);
                u_in = __int_as_float((int)(unsigned)mv);
                if (tk + 1 < NFSZ) mv = ldv64(&mbin[tk + 1]);   // prefetch next
            }

            float pre[8];
            if (layer == 0) {
                #pragma unroll
                for (int j = 0; j < 8; j++)
                    pre[j] = fmaf(whh_s[j], h_prev, gfc[j]);
            } else {
                #pragma unroll
                for (int j = 0; j < 8; j++)
                    pre[j] = fmaf(whh_s[j], h_prev, fmaf(wih_s[j], u_in, base_s[j]));
            }

            float partial = 0.f;
            #pragma unroll
            for (int m = 0; m < 2; m++) {
                float ei = ex2f(pre[m]);
                float ef = ex2f(pre[2 + m]);
                float gs = pre[4 + m];
                float eg = ex2f(negabsf(gs));
                float eo = ex2f(pre[6 + m]);
                float sf  = rcpf(1.f + ef);
                float mag = (1.f - eg) * rcpf((1.f + ei) * (1.f + eg));
                float itg = copysignf(mag, -gs);
                float c = (m == 0) ? cs0 : cs1;
                c = fmaf(sf, c, itg);
                float ec = ex2f(NL2E2 * fabsf(c));
                float hm = (1.f - ec) * rcpf((1.f + eo) * (1.f + ec));
                float hr = copysignf(hm, c);
                if (m == 0) { cs0 = c; partial = fmaf(hr, w0, partial); }
                else        { cs1 = c; partial = fmaf(hr, w1, partial); }
            }
            partial += __shfl_xor_sync(0xffffffffu, partial, 16);
            partial += __shfl_xor_sync(0xffffffffu, partial, 8);
            partial += __shfl_xor_sync(0xffffffffu, partial, 4);
            partial += __shfl_xor_sync(0xffffffffu, partial, 2);
            partial += __shfl_xor_sync(0xffffffffu, partial, 1);
            if (lane == 0) part[par][warp] = partial;
        }

        if (layer == 0) {
            #pragma unroll
            for (int j = 0; j < 8; j++) gfc[j] = gfn[j];
        }
        __syncthreads();
    }
}

// ---------------- launch ----------------

extern "C" void kernel_launch(void* const* d_in, const int* in_sizes, int n_in,
                              void* d_out, int out_size) {
    const float* x    = (const float*)d_in[0];
    const float* f    = (const float*)d_in[1];
    const float* Wih0 = (const float*)d_in[2];
    const float* Whh0 = (const float*)d_in[3];
    const float* bih0 = (const float*)d_in[4];
    const float* bhh0 = (const float*)d_in[5];
    const float* Whr0 = (const float*)d_in[6];
    const float* Wih1 = (const float*)d_in[7];
    const float* Whh1 = (const float*)d_in[8];
    const float* bih1 = (const float*)d_in[9];
    const float* bhh1 = (const float*)d_in[10];
    const float* Whr1 = (const float*)d_in[11];
    const float* Wih2 = (const float*)d_in[12];
    const float* Whh2 = (const float*)d_in[13];
    const float* bih2 = (const float*)d_in[14];
    const float* bhh2 = (const float*)d_in[15];
    const float* Whr2 = (const float*)d_in[16];

    gf_kernel<<<dim3(126, 4), 256>>>(f, Wih0);
    lstm_kernel<<<3 * BSZ, 128>>>(x,
                                  Wih0, Whh0, bih0, bhh0, Whr0,
                                  Wih1, Whh1, bih1, bhh1, Whr1,
                                  Wih2, Whh2, bih2, bhh2, Whr2,
                                  (float*)d_out);
}

// round 9
// speedup vs baseline: 1.0163x; 1.0163x over previous
#include <cuda_runtime.h>

#define NFSZ 1001
#define HSZ   256
#define BSZ   64
#define FD    128
#define INCH  16
#define G4    1024   // 4*H
#define INS0  144    // FD + INCH

// device-global scratch (allocation-free rule)
__device__ float g_Gf[NFSZ * G4];                // pre-scaled f-side gate pre-acts
__device__ unsigned long long g_mb[BSZ * 1024];  // layer0->layer1 mailbox {tag,val}

__device__ __forceinline__ float ex2f(float x) {
    float y; asm("ex2.approx.f32 %0, %1;" : "=f"(y) : "f"(x)); return y;
}
__device__ __forceinline__ float rcpf(float x) {
    float y; asm("rcp.approx.f32 %0, %1;" : "=f"(y) : "f"(x)); return y;
}
__device__ __forceinline__ float negabsf(float x) {
    return __int_as_float(__float_as_int(x) | 0x80000000);
}
__device__ __forceinline__ unsigned long long ldv64(const unsigned long long* p) {
    unsigned long long v;
    asm volatile("ld.volatile.global.b64 %0, [%1];" : "=l"(v) : "l"(p));
    return v;
}
__device__ __forceinline__ void stv64(unsigned long long* p, unsigned long long v) {
    asm volatile("st.volatile.global.b64 [%0], %1;" :: "l"(p), "l"(v) : "memory");
}
__device__ __forceinline__ unsigned smaddr(const void* p) {
    unsigned a;
    asm("{.reg .u64 t; cvta.to.shared.u64 t, %1; cvt.u32.u64 %0, t;}"
        : "=r"(a) : "l"(p));
    return a;
}
__device__ __forceinline__ unsigned long long ldvs64(unsigned a) {
    unsigned long long v;
    asm volatile("ld.volatile.shared.b64 %0, [%1];" : "=l"(v) : "r"(a));
    return v;
}
__device__ __forceinline__ void stvs64(unsigned a, unsigned long long v) {
    asm volatile("st.volatile.shared.b64 [%0], %1;" :: "r"(a), "l"(v));
}
__device__ __forceinline__ unsigned long long packtv(unsigned tag, float val) {
    return ((unsigned long long)tag << 32) | (unsigned)__float_as_int(val);
}
__device__ __forceinline__ float valof(unsigned long long v) {
    return __int_as_float((int)(unsigned)v);
}

#define L2E   1.4426950408889634f
#define NL2E2 -2.8853900817779268f

// ---------------- precompute: Gf = scale * (f @ Wf^T) ----------------
__global__ __launch_bounds__(256) void gf_kernel(const float* __restrict__ f,
                                                 const float* __restrict__ Wih0) {
    __shared__ float Wc[256][33];
    __shared__ float fs[8][32];
    const int tid = threadIdx.x;
    const int t0  = blockIdx.x * 8;
    const int gb  = blockIdx.y * 256;

    float acc[8] = {0.f,0.f,0.f,0.f,0.f,0.f,0.f,0.f};
    for (int kc = 0; kc < FD; kc += 32) {
        #pragma unroll
        for (int i = 0; i < 32; i++) {
            int e  = i * 256 + tid;
            int gl = e >> 5, kk = e & 31;
            Wc[gl][kk] = Wih0[(gb + gl) * INS0 + kc + kk];
        }
        {
            int tt = tid >> 5, kk = tid & 31;
            int t = t0 + tt;
            fs[tt][kk] = (t < NFSZ) ? f[t * FD + kc + kk] : 0.f;
        }
        __syncthreads();
        #pragma unroll 8
        for (int kk = 0; kk < 32; kk++) {
            float w = Wc[tid][kk];
            #pragma unroll
            for (int tt = 0; tt < 8; tt++) acc[tt] = fmaf(fs[tt][kk], w, acc[tt]);
        }
        __syncthreads();
    }
    float scale = (blockIdx.y == 2) ? NL2E2 : -L2E;
    #pragma unroll
    for (int tt = 0; tt < 8; tt++) {
        int t = t0 + tt;
        if (t < NFSZ) g_Gf[t * G4 + gb + tid] = acc[tt] * scale;
    }
}

// ---------------- main LSTM: 2 CTAs per batch, ZERO in-loop barriers ----------------
// blk even -> role A (layer0, 128 working threads); blk odd -> role B (layers 1+2,
// two warpgroups of 128). All sync via tagged 64-bit mailbox words:
//   intra-layer: parity-2 smem slots, tag = tick written
//   layer1->2 : full smem ring, slot t tagged t+1
//   layer0->1 : full gmem ring, slot t tagged t+1

// compute one unit pair + 5-level reduce; returns warp partial in 'partial'
#define UNIT_MATH(PRE, CS0, CS1, W0, W1, PARTIAL)                         \
    {                                                                     \
        float partial_ = 0.f;                                             \
        _Pragma("unroll")                                                 \
        for (int m = 0; m < 2; m++) {                                     \
            float ei = ex2f(PRE[m]);                                      \
            float ef = ex2f(PRE[2 + m]);                                  \
            float gs = PRE[4 + m];                                        \
            float eg = ex2f(negabsf(gs));                                 \
            float eo = ex2f(PRE[6 + m]);                                  \
            float sf  = rcpf(1.f + ef);                                   \
            float mag = (1.f - eg) * rcpf((1.f + ei) * (1.f + eg));       \
            float itg = copysignf(mag, -gs);                              \
            float c = (m == 0) ? CS0 : CS1;                               \
            c = fmaf(sf, c, itg);                                         \
            float ec = ex2f(NL2E2 * fabsf(c));                            \
            float hm = (1.f - ec) * rcpf((1.f + eo) * (1.f + ec));        \
            float hr = copysignf(hm, c);                                  \
            if (m == 0) { CS0 = c; partial_ = fmaf(hr, W0, partial_); }   \
            else        { CS1 = c; partial_ = fmaf(hr, W1, partial_); }   \
        }                                                                 \
        partial_ += __shfl_xor_sync(0xffffffffu, partial_, 16);           \
        partial_ += __shfl_xor_sync(0xffffffffu, partial_, 8);            \
        partial_ += __shfl_xor_sync(0xffffffffu, partial_, 4);            \
        partial_ += __shfl_xor_sync(0xffffffffu, partial_, 2);            \
        partial_ += __shfl_xor_sync(0xffffffffu, partial_, 1);            \
        PARTIAL = partial_;                                               \
    }

// spin-gather 4 tagged warp partials (parity offset RPOFF, expected tag EXP)
#define GATHER(XA, RPOFF, EXP, HOUT)                                      \
    {                                                                     \
        unsigned long long v0, v1, v2, v3;                                \
        do {                                                              \
            v0 = ldvs64((XA) + (RPOFF));                                  \
            v1 = ldvs64((XA) + (RPOFF) + 8);                              \
            v2 = ldvs64((XA) + (RPOFF) + 16);                             \
            v3 = ldvs64((XA) + (RPOFF) + 24);                             \
        } while ((unsigned)(v0 >> 32) != (EXP) ||                         \
                 (unsigned)(v1 >> 32) != (EXP) ||                         \
                 (unsigned)(v2 >> 32) != (EXP) ||                         \
                 (unsigned)(v3 >> 32) != (EXP));                          \
        HOUT = (valof(v0) + valof(v1)) + (valof(v2) + valof(v3));         \
    }

__global__ __launch_bounds__(256, 1) void lstm_kernel(
    const float* __restrict__ x,
    const float* __restrict__ Wih0, const float* __restrict__ Whh0,
    const float* __restrict__ bih0, const float* __restrict__ bhh0,
    const float* __restrict__ Whr0,
    const float* __restrict__ Wih1, const float* __restrict__ Whh1,
    const float* __restrict__ bih1, const float* __restrict__ bhh1,
    const float* __restrict__ Whr1,
    const float* __restrict__ Wih2, const float* __restrict__ Whh2,
    const float* __restrict__ bih2, const float* __restrict__ bhh2,
    const float* __restrict__ Whr2,
    float* __restrict__ out)
{
    __shared__ __align__(16) unsigned long long xch[2][2][4]; // [wg][parity][warp]
    __shared__ unsigned long long fwd[NFSZ];                  // layer1->2 ring

    const int b    = blockIdx.x >> 1;
    const int role = blockIdx.x & 1;
    const int tid  = threadIdx.x;

    // init tagged slots: tag 0xFFFFFFFF (matches tick-0 expect), val 0
    if (tid < 16) xch[tid >> 3][(tid >> 2) & 1][tid & 3] = 0xFFFFFFFF00000000ull;
    if (role == 1)
        for (int i = tid; i < NFSZ; i += 256) fwd[i] = 0ull;
    __syncthreads();   // one-time; loop below is barrier-free

    if (role == 0) {
        // ================= ROLE A : layer 0 =================
        if (tid >= 128) return;
        const int warp = tid >> 5, lane = tid & 31;
        const int u0   = tid * 2;

        float whh_s[8], base_s[8];
        #pragma unroll
        for (int j = 0; j < 8; j++) {
            int gate = j >> 1;
            int idx  = gate * HSZ + u0 + (j & 1);
            float sc = (gate == 2) ? NL2E2 : -L2E;
            whh_s[j] = Whh0[idx] * sc;
            float acc = bih0[idx] + bhh0[idx];
            #pragma unroll
            for (int kk = 0; kk < INCH; kk++)
                acc = fmaf(x[b * INCH + kk], Wih0[idx * INS0 + FD + kk], acc);
            base_s[j] = acc * sc;
        }
        const float w0 = Whr0[u0], w1 = Whr0[u0 + 1];
        float cs0 = 0.f, cs1 = 0.f;

        const unsigned xa = smaddr(&xch[0][0][0]);
        const unsigned myslot = xa + warp * 8;
        unsigned long long* mbout = &g_mb[b * 1024];

        float gA[8], gB[8];
        {
            const float* g0 = &g_Gf[u0];
            #pragma unroll
            for (int g4 = 0; g4 < 4; g4++) {
                float2 v = *(const float2*)(g0 + g4 * HSZ);
                gA[2 * g4]     = v.x + base_s[2 * g4];
                gA[2 * g4 + 1] = v.y + base_s[2 * g4 + 1];
            }
        }
        const float* gp = &g_Gf[G4 + u0];

#define ATICK(TK, GC, GN, PAR)                                                 \
        {                                                                      \
            const int tk_ = (TK);                                              \
            if (tk_ < NFSZ - 1) {                                              \
                _Pragma("unroll")                                              \
                for (int g4 = 0; g4 < 4; g4++) {                               \
                    float2 v = *(const float2*)(gp + g4 * HSZ);                \
                    GN[2 * g4]     = v.x + base_s[2 * g4];                     \
                    GN[2 * g4 + 1] = v.y + base_s[2 * g4 + 1];                 \
                }                                                              \
                gp += G4;                                                      \
            }                                                                  \
            float h_prev;                                                      \
            GATHER(xa, ((PAR) ^ 1) * 32, (unsigned)(tk_ - 1), h_prev)          \
            if (tid == 0 && tk_ >= 1)                                          \
                stv64(&mbout[tk_ - 1], packtv((unsigned)tk_, h_prev));         \
            if (tk_ < NFSZ) {                                                  \
                float pre[8];                                                  \
                _Pragma("unroll")                                              \
                for (int j = 0; j < 8; j++)                                    \
                    pre[j] = fmaf(whh_s[j], h_prev, GC[j]);                    \
                float partial;                                                 \
                UNIT_MATH(pre, cs0, cs1, w0, w1, partial)                      \
                if (lane == 0)                                                 \
                    stvs64(myslot + (PAR) * 32, packtv((unsigned)tk_, partial)); \
            }                                                                  \
        }

        for (int tk = 0; tk <= NFSZ; tk += 2) {     // 1002 iterations
            ATICK(tk,     gA, gB, 0)
            ATICK(tk + 1, gB, gA, 1)
        }
#undef ATICK
    } else {
        // ============ ROLE B : layer1 (wg0) + layer2 (wg1) ============
        const int wgi  = tid >> 7;
        const int wtid = tid & 127;
        const int warp = wtid >> 5, lane = wtid & 31;
        const int u0   = wtid * 2;

        const float* Whh = wgi ? Whh2 : Whh1;
        const float* Wih = wgi ? Wih2 : Wih1;
        const float* bih = wgi ? bih2 : bih1;
        const float* bhh = wgi ? bhh2 : bhh1;
        const float* Whr = wgi ? Whr2 : Whr1;

        float whh_s[8], base_s[8], wih_s[8];
        #pragma unroll
        for (int j = 0; j < 8; j++) {
            int gate = j >> 1;
            int idx  = gate * HSZ + u0 + (j & 1);
            float sc = (gate == 2) ? NL2E2 : -L2E;
            whh_s[j]  = Whh[idx] * sc;
            base_s[j] = (bih[idx] + bhh[idx]) * sc;
            wih_s[j]  = Wih[idx] * sc;
        }
        const float w0 = Whr[u0], w1 = Whr[u0 + 1];
        float cs0 = 0.f, cs1 = 0.f;

        const unsigned xa = smaddr(&xch[wgi][0][0]);
        const unsigned myslot = xa + warp * 8;
        const unsigned fwa = smaddr(&fwd[0]);
        unsigned long long* mbin = &g_mb[b * 1024];
        unsigned long long mv = (wgi == 0) ? ldv64(&mbin[0]) : 0ull;
        float* outp = out + b * NFSZ;

#define BTICK(TK, PAR)                                                         \
        {                                                                      \
            const int tk_ = (TK);                                              \
            float h_prev;                                                      \
            GATHER(xa, ((PAR) ^ 1) * 32, (unsigned)(tk_ - 1), h_prev)          \
            if (wtid == 0 && tk_ >= 1) {                                       \
                if (wgi == 0)                                                  \
                    stvs64(fwa + (tk_ - 1) * 8, packtv((unsigned)tk_, h_prev));\
                else                                                           \
                    outp[tk_ - 1] = h_prev;                                    \
            }                                                                  \
            if (tk_ < NFSZ) {                                                  \
                float u_in;                                                    \
                if (wgi == 0) {                                                \
                    const unsigned expf = (unsigned)(tk_ + 1);                 \
                    while ((unsigned)(mv >> 32) != expf)                       \
                        mv = ldv64(&mbin[tk_]);                                \
                    u_in = valof(mv);                                          \
                    if (tk_ + 1 < NFSZ) mv = ldv64(&mbin[tk_ + 1]);            \
                } else {                                                       \
                    const unsigned expf = (unsigned)(tk_ + 1);                 \
                    unsigned long long fv = ldvs64(fwa + tk_ * 8);             \
                    while ((unsigned)(fv >> 32) != expf)                       \
                        fv = ldvs64(fwa + tk_ * 8);                            \
                    u_in = valof(fv);                                          \
                }                                                              \
                float pre[8];                                                  \
                _Pragma("unroll")                                              \
                for (int j = 0; j < 8; j++)                                    \
                    pre[j] = fmaf(whh_s[j], h_prev,                            \
                                  fmaf(wih_s[j], u_in, base_s[j]));            \
                float partial;                                                 \
                UNIT_MATH(pre, cs0, cs1, w0, w1, partial)                      \
                if (lane == 0)                                                 \
                    stvs64(myslot + (PAR) * 32, packtv((unsigned)tk_, partial)); \
            }                                                                  \
        }

        for (int tk = 0; tk <= NFSZ; tk += 2) {     // 1002 iterations
            BTICK(tk,     0)
            BTICK(tk + 1, 1)
        }
#undef BTICK
    }
}

// ---------------- launch ----------------

extern "C" void kernel_launch(void* const* d_in, const int* in_sizes, int n_in,
                              void* d_out, int out_size) {
    const float* x    = (const float*)d_in[0];
    const float* f    = (const float*)d_in[1];
    const float* Wih0 = (const float*)d_in[2];
    const float* Whh0 = (const float*)d_in[3];
    const float* bih0 = (const float*)d_in[4];
    const float* bhh0 = (const float*)d_in[5];
    const float* Whr0 = (const float*)d_in[6];
    const float* Wih1 = (const float*)d_in[7];
    const float* Whh1 = (const float*)d_in[8];
    const float* bih1 = (const float*)d_in[9];
    const float* bhh1 = (const float*)d_in[10];
    const float* Whr1 = (const float*)d_in[11];
    const float* Wih2 = (const float*)d_in[12];
    const float* Whh2 = (const float*)d_in[13];
    const float* bih2 = (const float*)d_in[14];
    const float* bhh2 = (const float*)d_in[15];
    const float* Whr2 = (const float*)d_in[16];

    gf_kernel<<<dim3(126, 4), 256>>>(f, Wih0);
    lstm_kernel<<<2 * BSZ, 256>>>(x,
                                  Wih0, Whh0, bih0, bhh0, Whr0,
                                  Wih1, Whh1, bih1, bhh1, Whr1,
                                  Wih2, Whh2, bih2, bhh2, Whr2,
                                  (float*)d_out);
}